// round 16
// baseline (speedup 1.0000x reference)
#include <cuda_runtime.h>
#include <cuda_bf16.h>
#include <cstdint>

// ============================================================================
// Problem: content[64,256], motion[64,512,128] -> M=32768 tokens
//   L1: [M,384]x[384,256]+b1, leaky(0.2)   (content half hoisted to CW bias)
//   L2: [M,256]x[256,512]+b2, leaky(0.2)
//   L3: [M,512]x[512,1152]+b3 -> out fp32
// Strategy: bf16x3 emulated-fp32 GEMM on mma.sync.m16n8k16.
//   C = Ahi*Blo + Ahi*Bhi + Alo*Bhi (A2B2 dropped, ~4e-6 rel).
// R16 = R12 split launches (fusion refuted R13/R14), with 64x64 WARP TILES:
//   128 threads/CTA, 4 warps (2x2), acc[4][8][4]=128 regs (cap is 256 at
//   launch_bounds(128,2) -> no spill), 2 CTA/SM preserved.
//   LDSM/HMMA ratio 16/96 per ks (was 24/96) -> SMEM crossbar no longer binds.
// ============================================================================

__device__ __nv_bfloat16 g_mhi[4194304];     // motion [32768,128]
__device__ __nv_bfloat16 g_mlo[4194304];
__device__ __nv_bfloat16 g_h1hi[8388608];    // [32768,256]
__device__ __nv_bfloat16 g_h1lo[8388608];
__device__ __nv_bfloat16 g_h2hi[16777216];   // [32768,512]
__device__ __nv_bfloat16 g_h2lo[16777216];
__device__ __nv_bfloat16 g_w1hi[32768],  g_w1lo[32768];    // W1m^T [256,128]
__device__ __nv_bfloat16 g_w2hi[131072], g_w2lo[131072];   // [512,256]
__device__ __nv_bfloat16 g_w3hi[589824], g_w3lo[589824];   // [1152,512]
__device__ float         g_cw[16384];        // CW [64,256] = content@W1c + b1

// ---- helpers ----
__device__ __forceinline__ uint32_t smem_u32(const void* p) {
    uint32_t a;
    asm("{ .reg .u64 t; cvta.to.shared.u64 t, %1; cvt.u32.u64 %0, t; }"
        : "=r"(a) : "l"(p));
    return a;
}
__device__ __forceinline__ void cp16(uint32_t dst, const void* src) {
    asm volatile("cp.async.cg.shared.global [%0], [%1], 16;"
                 :: "r"(dst), "l"(src) : "memory");
}
#define CP_COMMIT() asm volatile("cp.async.commit_group;" ::: "memory")
#define CP_WAIT(n)  asm volatile("cp.async.wait_group %0;" :: "n"(n) : "memory")

__device__ __forceinline__ void ldsm4(uint32_t* r, uint32_t addr) {
    asm volatile("ldmatrix.sync.aligned.m8n8.x4.shared.b16 {%0,%1,%2,%3}, [%4];"
                 : "=r"(r[0]), "=r"(r[1]), "=r"(r[2]), "=r"(r[3]) : "r"(addr));
}
__device__ __forceinline__ void hmma(float* c, const uint32_t* a, const uint32_t* b) {
    asm volatile(
        "mma.sync.aligned.m16n8k16.row.col.f32.bf16.bf16.f32 "
        "{%0,%1,%2,%3}, {%4,%5,%6,%7}, {%8,%9}, {%0,%1,%2,%3};"
        : "+f"(c[0]), "+f"(c[1]), "+f"(c[2]), "+f"(c[3])
        : "r"(a[0]), "r"(a[1]), "r"(a[2]), "r"(a[3]), "r"(b[0]), "r"(b[1]));
}

// ============================================================================
// prep kernels (unchanged from R12)
// ============================================================================
__global__ void content_gemm(const float* __restrict__ content,
                             const float* __restrict__ W1,
                             const float* __restrict__ b1,
                             float* __restrict__ cw)
{
    __shared__ float crow[256];
    const int b = blockIdx.x;
    const int n = threadIdx.x;
    crow[n] = content[b * 256 + n];
    __syncthreads();
    float s = b1[n];
    #pragma unroll 8
    for (int k = 0; k < 256; ++k)
        s = fmaf(crow[k], W1[k * 256 + n], s);
    cw[b * 256 + n] = s;
}

__global__ void prep_motion(const float* __restrict__ motion,
                            __nv_bfloat16* __restrict__ hi,
                            __nv_bfloat16* __restrict__ lo)
{
    const int i = (blockIdx.x * 256 + threadIdx.x) * 4;
    const float4 v = *reinterpret_cast<const float4*>(motion + i);
    __nv_bfloat16 h0 = __float2bfloat16(v.x);
    __nv_bfloat16 h1 = __float2bfloat16(v.y);
    __nv_bfloat16 h2 = __float2bfloat16(v.z);
    __nv_bfloat16 h3 = __float2bfloat16(v.w);
    __nv_bfloat162 hv[2] = { __halves2bfloat162(h0, h1),
                             __halves2bfloat162(h2, h3) };
    __nv_bfloat162 lv[2] = {
        __halves2bfloat162(__float2bfloat16(v.x - __bfloat162float(h0)),
                           __float2bfloat16(v.y - __bfloat162float(h1))),
        __halves2bfloat162(__float2bfloat16(v.z - __bfloat162float(h2)),
                           __float2bfloat16(v.w - __bfloat162float(h3))) };
    *reinterpret_cast<uint2*>(hi + i) = *reinterpret_cast<uint2*>(hv);
    *reinterpret_cast<uint2*>(lo + i) = *reinterpret_cast<uint2*>(lv);
}

__global__ void prep_w(const float* __restrict__ W,
                       __nv_bfloat16* __restrict__ hi,
                       __nv_bfloat16* __restrict__ lo, int N, int K)
{
    __shared__ float t[32][33];
    const int nt = blockIdx.x * 32;
    const int kt = blockIdx.y * 32;
    const int tx = threadIdx.x;
    const int ty = threadIdx.y;
    #pragma unroll
    for (int i = 0; i < 32; i += 8)
        t[ty + i][tx] = W[(size_t)(kt + ty + i) * N + nt + tx];
    __syncthreads();
    #pragma unroll
    for (int i = 0; i < 32; i += 8) {
        const int n = nt + ty + i;
        const int k = kt + tx;
        const float v = t[tx][ty + i];
        const __nv_bfloat16 h = __float2bfloat16(v);
        hi[(size_t)n * K + k] = h;
        lo[(size_t)n * K + k] = __float2bfloat16(v - __bfloat162float(h));
    }
}

// ============================================================================
// bf16x3 GEMM. CTA tile 128x128, BK=32, XOR swizzle, 3-stage pipeline.
// 128 threads = 4 warps in 2(M)x2(N) grid, warp tile 64x64.
// acc[4][8][4] (128 regs) + a[4][4] + b[8][2]. launch_bounds(128,2).
// Per ks-step: 16 LDSM (A hi 4, Blo 4, Bhi 4, Alo 4), 96 HMMA.
// ============================================================================
#define TILE_B 8192                  // 128 rows * 64 B
#define STG_B  (4 * TILE_B)          // 32768 B per stage
#define NSTG   3

template<int K, int NTOT, bool LEAKY, bool WRITE_F32, bool ROWBIAS>
__global__ __launch_bounds__(128, 2)
void gemm_hmma(const __nv_bfloat16* __restrict__ Ahi,
               const __nv_bfloat16* __restrict__ Alo,
               const __nv_bfloat16* __restrict__ Bhi,
               const __nv_bfloat16* __restrict__ Blo,
               const float* __restrict__ bias,
               float* __restrict__ Cout,
               __nv_bfloat16* __restrict__ NxtHi,
               __nv_bfloat16* __restrict__ NxtLo)
{
    constexpr int KC = K / 32;

    extern __shared__ __nv_bfloat16 smem[];
    const uint32_t smem_base = smem_u32(smem);

    const int tid  = threadIdx.x;
    const int lane = tid & 31;
    const int wid  = tid >> 5;          // 0..3
    const int g    = lane >> 2;
    const int t2   = (lane & 3) * 2;
    const int wm   = (wid >> 1) * 64;   // 0,64
    const int wn   = (wid & 1) * 64;    // 0,64

    const int rowBlock = blockIdx.y * 128;
    const int colBlock = blockIdx.x * 128;

    float acc[4][8][4];
    #pragma unroll
    for (int i = 0; i < 4; i++)
        #pragma unroll
        for (int j = 0; j < 8; j++)
            #pragma unroll
            for (int r = 0; r < 4; r++) acc[i][j][r] = 0.0f;

    const int aRowT = ((lane >> 3) & 1) * 8 + (lane & 7);
    const int aColT = (lane >> 4) * 8;
    const int bRowT = ((lane >> 4) & 1) * 8 + (lane & 7);
    const int bColT = ((lane >> 3) & 1) * 8;
    const int aswz = (aRowT >> 1) & 3;
    const int bswz = (bRowT >> 1) & 3;

    // loader: 4 tiles x 512 cp16 = 2048 per chunk; 128 threads -> 16 each
    const int ldRow = tid >> 1;          // 0..63
    const int ldCh2 = (tid & 1) * 2;     // 0 or 2
    auto issue_chunk = [&](int c) {
        const int k0 = c * 32;
        const uint32_t sb = smem_base + (uint32_t)(c % NSTG) * STG_B;
        #pragma unroll
        for (int i = 0; i < 2; ++i) {
            const int r = ldRow + i * 64;
            #pragma unroll
            for (int j = 0; j < 2; ++j) {
                const int ch = ldCh2 + j;
                const uint32_t off =
                    (uint32_t)(r * 64 + ((ch ^ ((r >> 1) & 3)) * 16));
                const size_t ga = (size_t)(rowBlock + r) * K + k0 + ch * 8;
                const size_t gb = (size_t)(colBlock + r) * K + k0 + ch * 8;
                cp16(sb + off,                Ahi + ga);
                cp16(sb + TILE_B + off,       Alo + ga);
                cp16(sb + 2 * TILE_B + off,   Bhi + gb);
                cp16(sb + 3 * TILE_B + off,   Blo + gb);
            }
        }
        CP_COMMIT();
    };

    issue_chunk(0);
    issue_chunk(1);

    for (int c = 0; c < KC; ++c) {
        if (c + 1 < KC) { CP_WAIT(1); }
        else            { CP_WAIT(0); }
        __syncthreads();
        if (c + 2 < KC) issue_chunk(c + 2);

        const uint32_t sb   = smem_base + (uint32_t)(c % NSTG) * STG_B;
        const uint32_t sAhi = sb;
        const uint32_t sAlo = sb + TILE_B;
        const uint32_t sBhi = sb + 2 * TILE_B;
        const uint32_t sBlo = sb + 3 * TILE_B;

        #pragma unroll
        for (int ks = 0; ks < 2; ++ks) {
            const int kb = ks * 16;
            uint32_t a[4][4], b[8][2];
            const uint32_t asg = (uint32_t)((((kb + aColT) >> 3) ^ aswz) * 16);
            const uint32_t bsg = (uint32_t)((((kb + bColT) >> 3) ^ bswz) * 16);
            const uint32_t aOff = (uint32_t)((wm + aRowT) * 64) + asg;

            // ---- pass hl: Ahi * Blo ----
            #pragma unroll
            for (int mt = 0; mt < 4; ++mt)
                ldsm4(a[mt], sAhi + aOff + (uint32_t)(mt * 16 * 64));
            #pragma unroll
            for (int np = 0; np < 4; ++np) {
                uint32_t r4[4];
                ldsm4(r4, sBlo + (uint32_t)((wn + np * 16 + bRowT) * 64) + bsg);
                b[np * 2][0] = r4[0]; b[np * 2][1] = r4[1];
                b[np * 2 + 1][0] = r4[2]; b[np * 2 + 1][1] = r4[3];
            }
            #pragma unroll
            for (int mt = 0; mt < 4; ++mt)
                #pragma unroll
                for (int nt = 0; nt < 8; ++nt)
                    hmma(acc[mt][nt], a[mt], b[nt]);

            // ---- pass hh: Ahi * Bhi (a unchanged, reload b) ----
            #pragma unroll
            for (int np = 0; np < 4; ++np) {
                uint32_t r4[4];
                ldsm4(r4, sBhi + (uint32_t)((wn + np * 16 + bRowT) * 64) + bsg);
                b[np * 2][0] = r4[0]; b[np * 2][1] = r4[1];
                b[np * 2 + 1][0] = r4[2]; b[np * 2 + 1][1] = r4[3];
            }
            #pragma unroll
            for (int mt = 0; mt < 4; ++mt)
                #pragma unroll
                for (int nt = 0; nt < 8; ++nt)
                    hmma(acc[mt][nt], a[mt], b[nt]);

            // ---- pass lh: Alo * Bhi (b unchanged, reload a) ----
            #pragma unroll
            for (int mt = 0; mt < 4; ++mt)
                ldsm4(a[mt], sAlo + aOff + (uint32_t)(mt * 16 * 64));
            #pragma unroll
            for (int mt = 0; mt < 4; ++mt)
                #pragma unroll
                for (int nt = 0; nt < 8; ++nt)
                    hmma(acc[mt][nt], a[mt], b[nt]);
        }
    }

    __syncthreads();

    // ---- epilogue ----
    #pragma unroll
    for (int mt = 0; mt < 4; ++mt) {
        #pragma unroll
        for (int half = 0; half < 2; ++half) {
            const int grow = rowBlock + wm + mt * 16 + g + half * 8;
            const float* brow = ROWBIAS ? bias + (size_t)(grow >> 9) * NTOT
                                        : bias;
            #pragma unroll
            for (int nt = 0; nt < 8; ++nt) {
                const int gcol = colBlock + wn + nt * 8 + t2;
                float v0 = acc[mt][nt][half * 2 + 0] + brow[gcol];
                float v1 = acc[mt][nt][half * 2 + 1] + brow[gcol + 1];
                if (LEAKY) {
                    v0 = v0 >= 0.f ? v0 : 0.2f * v0;
                    v1 = v1 >= 0.f ? v1 : 0.2f * v1;
                }
                const size_t base = (size_t)grow * NTOT + gcol;
                if (WRITE_F32) {
                    float2 o; o.x = v0; o.y = v1;
                    *reinterpret_cast<float2*>(&Cout[base]) = o;
                } else {
                    __nv_bfloat16 h0 = __float2bfloat16(v0);
                    __nv_bfloat16 h1 = __float2bfloat16(v1);
                    __nv_bfloat16 l0 = __float2bfloat16(v0 - __bfloat162float(h0));
                    __nv_bfloat16 l1 = __float2bfloat16(v1 - __bfloat162float(h1));
                    *reinterpret_cast<__nv_bfloat162*>(&NxtHi[base]) =
                        __halves2bfloat162(h0, h1);
                    *reinterpret_cast<__nv_bfloat162*>(&NxtLo[base]) =
                        __halves2bfloat162(l0, l1);
                }
            }
        }
    }
}

// ============================================================================
// launcher
// ============================================================================
extern "C" void kernel_launch(void* const* d_in, const int* in_sizes, int n_in,
                              void* d_out, int out_size)
{
    (void)in_sizes; (void)n_in; (void)out_size;
    const float* content = (const float*)d_in[0];
    const float* motion  = (const float*)d_in[1];
    const float* W1 = (const float*)d_in[2];
    const float* b1 = (const float*)d_in[3];
    const float* W2 = (const float*)d_in[4];
    const float* b2 = (const float*)d_in[5];
    const float* W3 = (const float*)d_in[6];
    const float* b3 = (const float*)d_in[7];
    float* out = (float*)d_out;

    __nv_bfloat16 *mhi, *mlo, *h1hi, *h1lo, *h2hi, *h2lo;
    __nv_bfloat16 *w1hi, *w1lo, *w2hi, *w2lo, *w3hi, *w3lo;
    float* cw;
    cudaGetSymbolAddress((void**)&mhi, g_mhi);
    cudaGetSymbolAddress((void**)&mlo, g_mlo);
    cudaGetSymbolAddress((void**)&h1hi, g_h1hi);
    cudaGetSymbolAddress((void**)&h1lo, g_h1lo);
    cudaGetSymbolAddress((void**)&h2hi, g_h2hi);
    cudaGetSymbolAddress((void**)&h2lo, g_h2lo);
    cudaGetSymbolAddress((void**)&w1hi, g_w1hi);
    cudaGetSymbolAddress((void**)&w1lo, g_w1lo);
    cudaGetSymbolAddress((void**)&w2hi, g_w2hi);
    cudaGetSymbolAddress((void**)&w2lo, g_w2lo);
    cudaGetSymbolAddress((void**)&w3hi, g_w3hi);
    cudaGetSymbolAddress((void**)&w3lo, g_w3lo);
    cudaGetSymbolAddress((void**)&cw, g_cw);

    const int SMEM = NSTG * STG_B;  // 98304 B
    cudaFuncSetAttribute((const void*)gemm_hmma<128, 256, true, false, true>,
                         cudaFuncAttributeMaxDynamicSharedMemorySize, SMEM);
    cudaFuncSetAttribute((const void*)gemm_hmma<256, 512, true, false, false>,
                         cudaFuncAttributeMaxDynamicSharedMemorySize, SMEM);
    cudaFuncSetAttribute((const void*)gemm_hmma<512, 1152, false, true, false>,
                         cudaFuncAttributeMaxDynamicSharedMemorySize, SMEM);

    // ---- prep ----
    content_gemm<<<64, 256>>>(content, W1, b1, cw);
    prep_motion<<<4096, 256>>>(motion, mhi, mlo);
    prep_w<<<dim3(256 / 32, 128 / 32), dim3(32, 8)>>>(W1 + 256 * 256, w1hi, w1lo, 256, 128);
    prep_w<<<dim3(512 / 32, 256 / 32), dim3(32, 8)>>>(W2, w2hi, w2lo, 512, 256);
    prep_w<<<dim3(1152 / 32, 512 / 32), dim3(32, 8)>>>(W3, w3hi, w3lo, 1152, 512);

    // ---- GEMM chain ----
    gemm_hmma<128, 256, true, false, true><<<dim3(2, 256), 128, SMEM>>>(
        mhi, mlo, w1hi, w1lo, cw, nullptr, h1hi, h1lo);
    gemm_hmma<256, 512, true, false, false><<<dim3(4, 256), 128, SMEM>>>(
        h1hi, h1lo, w2hi, w2lo, b2, nullptr, h2hi, h2lo);
    gemm_hmma<512, 1152, false, true, false><<<dim3(9, 256), 128, SMEM>>>(
        h2hi, h2lo, w3hi, w3lo, b3, out, nullptr, nullptr);
}

// round 17
// speedup vs baseline: 1.8847x; 1.8847x over previous
#include <cuda_runtime.h>
#include <cuda_bf16.h>
#include <cstdint>

// ============================================================================
// Problem: content[64,256], motion[64,512,128] -> M=32768 tokens
//   L1: [M,384]x[384,256]+b1, leaky(0.2)   (content half hoisted to CW bias)
//   L2: [M,256]x[256,512]+b2, leaky(0.2)
//   L3: [M,512]x[512,1152]+b3 -> out fp32
// Strategy: bf16x3 emulated-fp32 GEMM on mma.sync.m16n8k16.
//   C = Ahi*Blo + Ahi*Bhi + Alo*Bhi (A2B2 dropped, ~4e-6 rel).
// R17 = R12 GEMM core EXACTLY (the proven local optimum: 128x128 CTA,
//   256 thr, 8 warps 2x4, warp tile 64x32, a16+b8 frags, XOR swizzle,
//   NSTG=3, 2 CTA/SM) + ALL prep merged into ONE kernel (block-range
//   dispatch) to remove 4 launch boundaries and sub-wave prep tails.
// Refuted permanently: bigger warp tiles (R16), 512-thr CTAs (R7),
//   extra fragment residency (R4/R8), persistent fusion (R13/R14).
// ============================================================================

__device__ __nv_bfloat16 g_mhi[4194304];     // motion [32768,128]
__device__ __nv_bfloat16 g_mlo[4194304];
__device__ __nv_bfloat16 g_h1hi[8388608];    // [32768,256]
__device__ __nv_bfloat16 g_h1lo[8388608];
__device__ __nv_bfloat16 g_h2hi[16777216];   // [32768,512]
__device__ __nv_bfloat16 g_h2lo[16777216];
__device__ __nv_bfloat16 g_w1hi[32768],  g_w1lo[32768];    // W1m^T [256,128]
__device__ __nv_bfloat16 g_w2hi[131072], g_w2lo[131072];   // [512,256]
__device__ __nv_bfloat16 g_w3hi[589824], g_w3lo[589824];   // [1152,512]
__device__ float         g_cw[16384];        // CW [64,256] = content@W1c + b1

// ---- helpers ----
__device__ __forceinline__ uint32_t smem_u32(const void* p) {
    uint32_t a;
    asm("{ .reg .u64 t; cvta.to.shared.u64 t, %1; cvt.u32.u64 %0, t; }"
        : "=r"(a) : "l"(p));
    return a;
}
__device__ __forceinline__ void cp16(uint32_t dst, const void* src) {
    asm volatile("cp.async.cg.shared.global [%0], [%1], 16;"
                 :: "r"(dst), "l"(src) : "memory");
}
#define CP_COMMIT() asm volatile("cp.async.commit_group;" ::: "memory")
#define CP_WAIT(n)  asm volatile("cp.async.wait_group %0;" :: "n"(n) : "memory")

__device__ __forceinline__ void ldsm4(uint32_t* r, uint32_t addr) {
    asm volatile("ldmatrix.sync.aligned.m8n8.x4.shared.b16 {%0,%1,%2,%3}, [%4];"
                 : "=r"(r[0]), "=r"(r[1]), "=r"(r[2]), "=r"(r[3]) : "r"(addr));
}
__device__ __forceinline__ void hmma(float* c, const uint32_t* a, const uint32_t* b) {
    asm volatile(
        "mma.sync.aligned.m16n8k16.row.col.f32.bf16.bf16.f32 "
        "{%0,%1,%2,%3}, {%4,%5,%6,%7}, {%8,%9}, {%0,%1,%2,%3};"
        : "+f"(c[0]), "+f"(c[1]), "+f"(c[2]), "+f"(c[3])
        : "r"(a[0]), "r"(a[1]), "r"(a[2]), "r"(a[3]), "r"(b[0]), "r"(b[1]));
}

// ============================================================================
// merged prep kernel: one launch, block-range dispatch.
//   [0,4096)            motion split (float4)
//   [4096,4160)         content GEMM rows (exact fp32 CW)
//   [4160,4192)         W1m^T tiles (N=256,K=128, 8x4)
//   [4192,4320)         W2^T  tiles (N=512,K=256, 16x8)
//   [4320,4896)         W3^T  tiles (N=1152,K=512, 36x16)
// ============================================================================
#define PB_MOTION 4096
#define PB_CG     (PB_MOTION + 64)
#define PB_W1     (PB_CG + 32)
#define PB_W2     (PB_W1 + 128)
#define PB_W3     (PB_W2 + 576)

__device__ __forceinline__ void prep_w_tile(
    const float* __restrict__ W, __nv_bfloat16* __restrict__ hi,
    __nv_bfloat16* __restrict__ lo, int N, int K, int bx, int by,
    float (*t)[33], int tid)
{
    const int nt = bx * 32;
    const int kt = by * 32;
    const int tx = tid & 31;
    const int ty = tid >> 5;    // 0..7
    #pragma unroll
    for (int i = 0; i < 32; i += 8)
        t[ty + i][tx] = W[(size_t)(kt + ty + i) * N + nt + tx];
    __syncthreads();
    #pragma unroll
    for (int i = 0; i < 32; i += 8) {
        const int n = nt + ty + i;
        const int k = kt + tx;
        const float v = t[tx][ty + i];
        const __nv_bfloat16 h = __float2bfloat16(v);
        hi[(size_t)n * K + k] = h;
        lo[(size_t)n * K + k] = __float2bfloat16(v - __bfloat162float(h));
    }
}

__global__ __launch_bounds__(256)
void prep_all(const float* __restrict__ content,
              const float* __restrict__ motion,
              const float* __restrict__ W1,
              const float* __restrict__ b1,
              const float* __restrict__ W2,
              const float* __restrict__ W3,
              __nv_bfloat16* __restrict__ mhi,
              __nv_bfloat16* __restrict__ mlo,
              __nv_bfloat16* __restrict__ w1hi,
              __nv_bfloat16* __restrict__ w1lo,
              __nv_bfloat16* __restrict__ w2hi,
              __nv_bfloat16* __restrict__ w2lo,
              __nv_bfloat16* __restrict__ w3hi,
              __nv_bfloat16* __restrict__ w3lo,
              float* __restrict__ cw)
{
    __shared__ float sh[32][33];           // transpose tile (also reused below)
    const int blk = blockIdx.x;
    const int tid = threadIdx.x;

    if (blk < PB_MOTION) {
        // ---- motion hi/lo split, float4 ----
        const int i = (blk * 256 + tid) * 4;
        const float4 v = *reinterpret_cast<const float4*>(motion + i);
        __nv_bfloat16 h0 = __float2bfloat16(v.x);
        __nv_bfloat16 h1 = __float2bfloat16(v.y);
        __nv_bfloat16 h2 = __float2bfloat16(v.z);
        __nv_bfloat16 h3 = __float2bfloat16(v.w);
        __nv_bfloat162 hv[2] = { __halves2bfloat162(h0, h1),
                                 __halves2bfloat162(h2, h3) };
        __nv_bfloat162 lv[2] = {
            __halves2bfloat162(__float2bfloat16(v.x - __bfloat162float(h0)),
                               __float2bfloat16(v.y - __bfloat162float(h1))),
            __halves2bfloat162(__float2bfloat16(v.z - __bfloat162float(h2)),
                               __float2bfloat16(v.w - __bfloat162float(h3))) };
        *reinterpret_cast<uint2*>(mhi + i) = *reinterpret_cast<uint2*>(hv);
        *reinterpret_cast<uint2*>(mlo + i) = *reinterpret_cast<uint2*>(lv);
    } else if (blk < PB_CG) {
        // ---- CW[64,256] = content @ W1[0:256,:] + b1 (exact fp32) ----
        float* crow = &sh[0][0];           // 256 floats
        const int b = blk - PB_MOTION;
        const int n = tid;
        crow[n] = content[b * 256 + n];
        __syncthreads();
        float s = b1[n];
        #pragma unroll 8
        for (int k = 0; k < 256; ++k)
            s = fmaf(crow[k], W1[k * 256 + n], s);
        cw[b * 256 + n] = s;
    } else if (blk < PB_W1) {
        const int u = blk - PB_CG;         // 0..31 (8x4)
        prep_w_tile(W1 + 256 * 256, w1hi, w1lo, 256, 128, u & 7, u >> 3, sh, tid);
    } else if (blk < PB_W2) {
        const int u = blk - PB_W1;         // 0..127 (16x8)
        prep_w_tile(W2, w2hi, w2lo, 512, 256, u & 15, u >> 4, sh, tid);
    } else {
        const int u = blk - PB_W2;         // 0..575 (36x16)
        prep_w_tile(W3, w3hi, w3lo, 1152, 512, u % 36, u / 36, sh, tid);
    }
}

// ============================================================================
// bf16x3 GEMM — byte-identical to R12. CTA tile 128x128, BK=32, XOR swizzle,
// 3-stage pipeline, fragments a[4][4]+b[4][2] only, 2 CTA/SM.
// Pass order hl -> hh -> lh (12 LDSM per ks-step).
// ============================================================================
#define TILE_B 8192                  // 128 rows * 64 B
#define STG_B  (4 * TILE_B)          // 32768 B per stage
#define NSTG   3

template<int K, int NTOT, bool LEAKY, bool WRITE_F32, bool ROWBIAS>
__global__ __launch_bounds__(256, 2)
void gemm_hmma(const __nv_bfloat16* __restrict__ Ahi,
               const __nv_bfloat16* __restrict__ Alo,
               const __nv_bfloat16* __restrict__ Bhi,
               const __nv_bfloat16* __restrict__ Blo,
               const float* __restrict__ bias,
               float* __restrict__ Cout,
               __nv_bfloat16* __restrict__ NxtHi,
               __nv_bfloat16* __restrict__ NxtLo)
{
    constexpr int KC = K / 32;

    extern __shared__ __nv_bfloat16 smem[];
    const uint32_t smem_base = smem_u32(smem);

    const int tid  = threadIdx.x;
    const int lane = tid & 31;
    const int wid  = tid >> 5;
    const int g    = lane >> 2;
    const int t2   = (lane & 3) * 2;
    const int wm   = (wid >> 2) * 64;
    const int wn   = (wid & 3) * 32;

    const int rowBlock = blockIdx.y * 128;
    const int colBlock = blockIdx.x * 128;

    float acc[4][4][4];
    #pragma unroll
    for (int i = 0; i < 4; i++)
        #pragma unroll
        for (int j = 0; j < 4; j++)
            #pragma unroll
            for (int r = 0; r < 4; r++) acc[i][j][r] = 0.0f;

    const int aRowT = ((lane >> 3) & 1) * 8 + (lane & 7);
    const int aColT = (lane >> 4) * 8;
    const int bRowT = ((lane >> 4) & 1) * 8 + (lane & 7);
    const int bColT = ((lane >> 3) & 1) * 8;
    const int aswz = (aRowT >> 1) & 3;
    const int bswz = (bRowT >> 1) & 3;

    const int ldRow = tid >> 2;
    const int ldCh  = tid & 3;
    auto issue_chunk = [&](int c) {
        const int k0 = c * 32;
        const uint32_t sb = smem_base + (uint32_t)(c % NSTG) * STG_B;
        #pragma unroll
        for (int i = 0; i < 2; ++i) {
            const int r = ldRow + i * 64;
            const uint32_t off =
                (uint32_t)(r * 64 + ((ldCh ^ ((r >> 1) & 3)) * 16));
            const size_t ga = (size_t)(rowBlock + r) * K + k0 + ldCh * 8;
            const size_t gb = (size_t)(colBlock + r) * K + k0 + ldCh * 8;
            cp16(sb + off,                Ahi + ga);
            cp16(sb + TILE_B + off,       Alo + ga);
            cp16(sb + 2 * TILE_B + off,   Bhi + gb);
            cp16(sb + 3 * TILE_B + off,   Blo + gb);
        }
        CP_COMMIT();
    };

    issue_chunk(0);
    issue_chunk(1);

    for (int c = 0; c < KC; ++c) {
        if (c + 1 < KC) { CP_WAIT(1); }
        else            { CP_WAIT(0); }
        __syncthreads();
        if (c + 2 < KC) issue_chunk(c + 2);

        const uint32_t sb   = smem_base + (uint32_t)(c % NSTG) * STG_B;
        const uint32_t sAhi = sb;
        const uint32_t sAlo = sb + TILE_B;
        const uint32_t sBhi = sb + 2 * TILE_B;
        const uint32_t sBlo = sb + 3 * TILE_B;

        #pragma unroll
        for (int ks = 0; ks < 2; ++ks) {
            const int kb = ks * 16;
            uint32_t a[4][4], b[4][2];
            const uint32_t asg = (uint32_t)((((kb + aColT) >> 3) ^ aswz) * 16);
            const uint32_t bsg = (uint32_t)((((kb + bColT) >> 3) ^ bswz) * 16);
            const uint32_t aOff  = (uint32_t)((wm + aRowT) * 64) + asg;
            const uint32_t bOff0 = (uint32_t)((wn + bRowT) * 64) + bsg;
            const uint32_t bOff1 = (uint32_t)((wn + 16 + bRowT) * 64) + bsg;

            // ---- pass hl: Ahi * Blo ----
            #pragma unroll
            for (int mt = 0; mt < 4; ++mt)
                ldsm4(a[mt], sAhi + aOff + (uint32_t)(mt * 16 * 64));
            {
                uint32_t r4[4];
                ldsm4(r4, sBlo + bOff0);
                b[0][0] = r4[0]; b[0][1] = r4[1];
                b[1][0] = r4[2]; b[1][1] = r4[3];
                ldsm4(r4, sBlo + bOff1);
                b[2][0] = r4[0]; b[2][1] = r4[1];
                b[3][0] = r4[2]; b[3][1] = r4[3];
            }
            #pragma unroll
            for (int mt = 0; mt < 4; ++mt)
                #pragma unroll
                for (int nt = 0; nt < 4; ++nt)
                    hmma(acc[mt][nt], a[mt], b[nt]);

            // ---- pass hh: Ahi * Bhi (a unchanged, reload b) ----
            {
                uint32_t r4[4];
                ldsm4(r4, sBhi + bOff0);
                b[0][0] = r4[0]; b[0][1] = r4[1];
                b[1][0] = r4[2]; b[1][1] = r4[3];
                ldsm4(r4, sBhi + bOff1);
                b[2][0] = r4[0]; b[2][1] = r4[1];
                b[3][0] = r4[2]; b[3][1] = r4[3];
            }
            #pragma unroll
            for (int mt = 0; mt < 4; ++mt)
                #pragma unroll
                for (int nt = 0; nt < 4; ++nt)
                    hmma(acc[mt][nt], a[mt], b[nt]);

            // ---- pass lh: Alo * Bhi (b unchanged, reload a) ----
            #pragma unroll
            for (int mt = 0; mt < 4; ++mt)
                ldsm4(a[mt], sAlo + aOff + (uint32_t)(mt * 16 * 64));
            #pragma unroll
            for (int mt = 0; mt < 4; ++mt)
                #pragma unroll
                for (int nt = 0; nt < 4; ++nt)
                    hmma(acc[mt][nt], a[mt], b[nt]);
        }
    }

    __syncthreads();

    // ---- epilogue ----
    #pragma unroll
    for (int mt = 0; mt < 4; ++mt) {
        #pragma unroll
        for (int half = 0; half < 2; ++half) {
            const int grow = rowBlock + wm + mt * 16 + g + half * 8;
            const float* brow = ROWBIAS ? bias + (size_t)(grow >> 9) * NTOT
                                        : bias;
            #pragma unroll
            for (int nt = 0; nt < 4; ++nt) {
                const int gcol = colBlock + wn + nt * 8 + t2;
                float v0 = acc[mt][nt][half * 2 + 0] + brow[gcol];
                float v1 = acc[mt][nt][half * 2 + 1] + brow[gcol + 1];
                if (LEAKY) {
                    v0 = v0 >= 0.f ? v0 : 0.2f * v0;
                    v1 = v1 >= 0.f ? v1 : 0.2f * v1;
                }
                const size_t base = (size_t)grow * NTOT + gcol;
                if (WRITE_F32) {
                    float2 o; o.x = v0; o.y = v1;
                    *reinterpret_cast<float2*>(&Cout[base]) = o;
                } else {
                    __nv_bfloat16 h0 = __float2bfloat16(v0);
                    __nv_bfloat16 h1 = __float2bfloat16(v1);
                    __nv_bfloat16 l0 = __float2bfloat16(v0 - __bfloat162float(h0));
                    __nv_bfloat16 l1 = __float2bfloat16(v1 - __bfloat162float(h1));
                    *reinterpret_cast<__nv_bfloat162*>(&NxtHi[base]) =
                        __halves2bfloat162(h0, h1);
                    *reinterpret_cast<__nv_bfloat162*>(&NxtLo[base]) =
                        __halves2bfloat162(l0, l1);
                }
            }
        }
    }
}

// ============================================================================
// launcher
// ============================================================================
extern "C" void kernel_launch(void* const* d_in, const int* in_sizes, int n_in,
                              void* d_out, int out_size)
{
    (void)in_sizes; (void)n_in; (void)out_size;
    const float* content = (const float*)d_in[0];
    const float* motion  = (const float*)d_in[1];
    const float* W1 = (const float*)d_in[2];
    const float* b1 = (const float*)d_in[3];
    const float* W2 = (const float*)d_in[4];
    const float* b2 = (const float*)d_in[5];
    const float* W3 = (const float*)d_in[6];
    const float* b3 = (const float*)d_in[7];
    float* out = (float*)d_out;

    __nv_bfloat16 *mhi, *mlo, *h1hi, *h1lo, *h2hi, *h2lo;
    __nv_bfloat16 *w1hi, *w1lo, *w2hi, *w2lo, *w3hi, *w3lo;
    float* cw;
    cudaGetSymbolAddress((void**)&mhi, g_mhi);
    cudaGetSymbolAddress((void**)&mlo, g_mlo);
    cudaGetSymbolAddress((void**)&h1hi, g_h1hi);
    cudaGetSymbolAddress((void**)&h1lo, g_h1lo);
    cudaGetSymbolAddress((void**)&h2hi, g_h2hi);
    cudaGetSymbolAddress((void**)&h2lo, g_h2lo);
    cudaGetSymbolAddress((void**)&w1hi, g_w1hi);
    cudaGetSymbolAddress((void**)&w1lo, g_w1lo);
    cudaGetSymbolAddress((void**)&w2hi, g_w2hi);
    cudaGetSymbolAddress((void**)&w2lo, g_w2lo);
    cudaGetSymbolAddress((void**)&w3hi, g_w3hi);
    cudaGetSymbolAddress((void**)&w3lo, g_w3lo);
    cudaGetSymbolAddress((void**)&cw, g_cw);

    const int SMEM = NSTG * STG_B;  // 98304 B
    cudaFuncSetAttribute((const void*)gemm_hmma<128, 256, true, false, true>,
                         cudaFuncAttributeMaxDynamicSharedMemorySize, SMEM);
    cudaFuncSetAttribute((const void*)gemm_hmma<256, 512, true, false, false>,
                         cudaFuncAttributeMaxDynamicSharedMemorySize, SMEM);
    cudaFuncSetAttribute((const void*)gemm_hmma<512, 1152, false, true, false>,
                         cudaFuncAttributeMaxDynamicSharedMemorySize, SMEM);

    // ---- merged prep: one launch covers motion split, content GEMM, and
    //      all three weight transposes ----
    prep_all<<<PB_W3, 256>>>(content, motion, W1, b1, W2, W3,
                             mhi, mlo, w1hi, w1lo, w2hi, w2lo, w3hi, w3lo, cw);

    // ---- GEMM chain (R12 exact) ----
    gemm_hmma<128, 256, true, false, true><<<dim3(2, 256), 256, SMEM>>>(
        mhi, mlo, w1hi, w1lo, cw, nullptr, h1hi, h1lo);
    gemm_hmma<256, 512, true, false, false><<<dim3(4, 256), 256, SMEM>>>(
        h1hi, h1lo, w2hi, w2lo, b2, nullptr, h2hi, h2lo);
    gemm_hmma<512, 1152, false, true, false><<<dim3(9, 256), 256, SMEM>>>(
        h2hi, h2lo, w3hi, w3lo, b3, out, nullptr, nullptr);
}